// round 1
// baseline (speedup 1.0000x reference)
#include <cuda_runtime.h>
#include <math.h>

#define NB 8

__constant__ float c_START_Y[NB] = {0.1f, 0.2f, 0.3f, 0.4f, 0.5f, 0.6f, 0.7f, 0.8f};
__constant__ float c_START_X[NB] = {0.8f, 0.7f, 0.6f, 0.5f, 0.4f, 0.3f, 0.2f, 0.1f};
__constant__ int   c_SIDE[NB]    = {1, 0, 1, 0, 1, 0, 1, 0};

// Per-(blob, image) splat params: y, x, alpha', beta', gamma'  (exponent-form, log2e folded in)
#define MAX_B 4096
__device__ float g_params[NB * MAX_B * 5];

__device__ __forceinline__ float sigmoidf_(float v) {
    return 1.0f / (1.0f + __expf(-v));
}

// ---------------------------------------------------------------------------
// Encode: per-blob MLP over batch, then fold splat math into quadratic-form
// coefficients.  grid = (ceil(B/4), NB), block = (64, 4).
// ---------------------------------------------------------------------------
__global__ void encode_kernel(const float* __restrict__ positions,
                              const float* __restrict__ W1, const float* __restrict__ b1,
                              const float* __restrict__ W2, const float* __restrict__ b2,
                              const float* __restrict__ W3, const float* __restrict__ b3,
                              const float* __restrict__ scale_ptr, int B)
{
    const int i  = blockIdx.y;            // blob
    const int ty = threadIdx.y;           // 0..3 (batch sub-index)
    const int k  = threadIdx.x;           // 0..63 (hidden unit)
    const int b  = blockIdx.x * 4 + ty;   // batch element
    const bool valid = (b < B);

    __shared__ float sh_h[4][64];
    __shared__ float sh_bd[4][5];

    // ---- layer 1: 3 -> 64, relu ----
    float h = 0.0f;
    if (valid) {
        const float* p = positions + (size_t)b * 6 + (c_SIDE[i] ? 0 : 3);
        float p0 = p[0] * 100.0f, p1 = p[1] * 100.0f, p2 = p[2] * 100.0f;
        const float* w1 = W1 + (size_t)i * 3 * 64;
        h = fmaf(p0, w1[k], fmaf(p1, w1[64 + k], fmaf(p2, w1[128 + k], b1[i * 64 + k])));
        h = fmaxf(h, 0.0f);
    }
    sh_h[ty][k] = h;
    __syncthreads();

    // ---- layer 2: 64 -> 64, relu ----
    float acc = b2[i * 64 + k];
    {
        const float* w2 = W2 + (size_t)i * 64 * 64 + k;
        #pragma unroll 8
        for (int hh = 0; hh < 64; hh++)
            acc = fmaf(sh_h[ty][hh], w2[hh * 64], acc);
        acc = fmaxf(acc, 0.0f);
    }
    __syncthreads();
    sh_h[ty][k] = acc;
    __syncthreads();

    // ---- layer 3: 64 -> 5 ----
    if (k < 5) {
        float o = b3[i * 5 + k];
        const float* w3 = W3 + (size_t)i * 64 * 5 + k;
        #pragma unroll 8
        for (int hh = 0; hh < 64; hh++)
            o = fmaf(sh_h[ty][hh], w3[hh * 5], o);
        sh_bd[ty][k] = o;
    }
    __syncthreads();

    // ---- epilogue: blob params -> quadratic-form coefficients ----
    if (k == 0 && valid) {
        float bd0 = sh_bd[ty][0], bd1 = sh_bd[ty][1], bd2 = sh_bd[ty][2];
        float bd3 = sh_bd[ty][3], bd4 = sh_bd[ty][4];
        float scale = *scale_ptr;

        float y  = sigmoidf_(bd0) + c_START_Y[i];
        float x  = sigmoidf_(bd1) + c_START_X[i];
        float s  = (bd2 + 0.05f) * scale;
        float a  = 0.5f + sigmoidf_(bd3) * 1.5f;
        float th = sigmoidf_(bd4) * 3.14159265358979323846f;

        float sa = s * a + 1e-6f;              // major sigma
        float sb = s / (a + 1e-6f) + 1e-6f;    // minor sigma
        float A  = 0.5f / (sa * sa);
        float Bq = 0.5f / (sb * sb);

        float sn, c;
        sincosf(th, &sn, &c);

        // exp(-(alpha*dy^2 + beta*dx^2 + gamma*dy*dx)) == exp2(al*dy^2 + be*dx^2 + ga*dy*dx)
        const float L = 1.4426950408889634f;   // log2(e)
        float al = -L * (A * c * c + Bq * sn * sn);
        float be = -L * (A * sn * sn + Bq * c * c);
        float ga = -2.0f * L * (A - Bq) * c * sn;

        float* o = g_params + ((size_t)i * B + b) * 5;
        o[0] = y; o[1] = x; o[2] = al; o[3] = be; o[4] = ga;
    }
}

// ---------------------------------------------------------------------------
// Splat: each block = 8 rows of one image; 32 threads per row, each thread
// walks T/32 columns of its row.  Per pixel-blob: 2 FMA (1-D quadratic in w)
// + 1 MUFU.EX2 + 1 blend FMA.
// grid = (T/8, B), block = 256.
// ---------------------------------------------------------------------------
__global__ void __launch_bounds__(256) splat_kernel(float* __restrict__ out,
                                                    int B, int T, float invT)
{
    const int b    = blockIdx.y;
    const int tid  = threadIdx.x;
    const int lane = tid & 31;
    const int r    = tid >> 5;                 // 0..7
    const int row  = blockIdx.x * 8 + r;

    __shared__ float sp[NB * 5];
    if (tid < NB * 5) {
        int i = tid / 5, f = tid - i * 5;
        sp[tid] = g_params[((size_t)i * B + b) * 5 + f];
    }
    __syncthreads();
    if (row >= T) return;

    const float rowc = ((float)row + 0.5f) * invT;

    float K2[NB], K1[NB], K0[NB];
    #pragma unroll
    for (int i = 0; i < NB; i++) {
        float y  = sp[i * 5 + 0];
        float x  = sp[i * 5 + 1];
        float al = sp[i * 5 + 2];
        float be = sp[i * 5 + 3];
        float ga = sp[i * 5 + 4];
        float dy = rowc - y;
        // e(w) = be*(w-x)^2 + ga*dy*(w-x) + al*dy^2
        //      = K2*w^2 + K1*w + K0
        K2[i] = be;
        K1[i] = fmaf(ga, dy, -2.0f * be * x);
        float m = fmaf(al, dy, -(ga * x));
        K0[i] = fmaf(m, dy, be * x * x);
    }

    float* orow = out + ((size_t)b * T + row) * T;
    const int nj = (T + 31) >> 5;

    #pragma unroll 2
    for (int j = 0; j < nj; j++) {
        int col = lane + (j << 5);
        if (col >= T) break;
        float w = ((float)col + 0.5f) * invT;
        float img = 0.0f;
        #pragma unroll
        for (int i = 0; i < NB; i++) {
            float e = fmaf(fmaf(K2[i], w, K1[i]), w, K0[i]);
            float cur;
            asm("ex2.approx.ftz.f32 %0, %1;" : "=f"(cur) : "f"(e));
            img = fmaf(img, cur, cur);        // img = img*cur + cur (reference blend order)
        }
        orow[col] = img;
    }
}

// ---------------------------------------------------------------------------
extern "C" void kernel_launch(void* const* d_in, const int* in_sizes, int n_in,
                              void* d_out, int out_size)
{
    const float* positions = (const float*)d_in[0];
    const float* W1 = (const float*)d_in[1];
    const float* b1 = (const float*)d_in[2];
    const float* W2 = (const float*)d_in[3];
    const float* b2 = (const float*)d_in[4];
    const float* W3 = (const float*)d_in[5];
    const float* b3 = (const float*)d_in[6];
    const float* scale = (const float*)d_in[n_in - 1];   // blobs_scale_factor (last input)

    int B = in_sizes[0] / 6;
    if (B > MAX_B) B = MAX_B;
    int T = (int)(sqrt((double)out_size / (double)B) + 0.5);

    dim3 egrid((B + 3) / 4, NB);
    dim3 eblock(64, 4);
    encode_kernel<<<egrid, eblock>>>(positions, W1, b1, W2, b2, W3, b3, scale, B);

    dim3 sgrid((T + 7) / 8, B);
    splat_kernel<<<sgrid, 256>>>((float*)d_out, B, T, 1.0f / (float)T);
}